// round 1
// baseline (speedup 1.0000x reference)
#include <cuda_runtime.h>

#define BB 64
#define FF 128
#define LL 8192
#define KK 16

// Scratch for per-(batch,half) partial logits max: [128 blocks][8192]
__device__ float g_partial[128 * LL];

// ---------------------------------------------------------------------------
// Kernel 1: causal conv. I[b,f,t] = bias[f] + sum_k W[f,k] * x[b, t-15+k]
// Grid (16, 64), 128 threads. Each thread owns 4 consecutive t for all 128 f.
// x window in registers, W/bias via broadcast LDS -> FFMA-pipe bound.
// ---------------------------------------------------------------------------
__global__ __launch_bounds__(128) void conv_kernel(
    const float* __restrict__ x, const float* __restrict__ W,
    const float* __restrict__ bias, float* __restrict__ I)
{
    __shared__ float sx[512 + 15];
    __shared__ float sw[FF * KK];
    __shared__ float sb[FF];
    const int tid = threadIdx.x;
    const int b   = blockIdx.y;
    const int t0  = blockIdx.x * 512;
    const float* xb = x + (size_t)b * LL;

    for (int i = tid; i < 512 + 15; i += 128) {
        int g = t0 - 15 + i;
        sx[i] = (g >= 0) ? xb[g] : 0.0f;
    }
    for (int i = tid; i < FF * KK; i += 128) sw[i] = W[i];
    if (tid < FF) sb[tid] = bias[tid];
    __syncthreads();

    float xr[19];
    const int tl = tid * 4;
#pragma unroll
    for (int j = 0; j < 19; ++j) xr[j] = sx[tl + j];

    const size_t base = ((size_t)b * FF) * LL + (size_t)t0 + tl;
    for (int f = 0; f < FF; ++f) {
        float bv = sb[f];
        float a0 = bv, a1 = bv, a2 = bv, a3 = bv;
#pragma unroll
        for (int k = 0; k < KK; ++k) {
            float w = sw[f * KK + k];
            a0 = fmaf(w, xr[k],     a0);
            a1 = fmaf(w, xr[k + 1], a1);
            a2 = fmaf(w, xr[k + 2], a2);
            a3 = fmaf(w, xr[k + 3], a3);
        }
        *(float4*)(I + base + (size_t)f * LL) = make_float4(a0, a1, a2, a3);
    }
}

// ---------------------------------------------------------------------------
// Kernel 2: LIF scan + SMEM-transposed coalesced stores + fused partial logits.
// Grid 128 (= batch*2 halves), 64 threads (one filter chain each).
// Register ring of 8 float4 prefetches hides DRAM latency for the I stream.
// Every 32 timesteps: transpose tiles -> coalesced STG + column max.
// ---------------------------------------------------------------------------
__global__ __launch_bounds__(64) void lif_kernel(
    const float* __restrict__ I, float* __restrict__ vpre_out,
    float* __restrict__ v_out, float* __restrict__ s_out)
{
    __shared__ float tvp[64 * 36];   // v_pre tile [f][t], stride 36 (16B aligned)
    __shared__ float tvn[64 * 36];   // v (post-reset) tile
    __shared__ float tsp[64 * 36];   // spike tile
    __shared__ float pmax[64];

    const int tid = threadIdx.x;
    const int b   = blockIdx.x >> 1;
    const int h   = blockIdx.x & 1;
    const size_t row = ((size_t)(b * FF + h * 64 + tid)) * LL;
    const float4* __restrict__ Ir = (const float4*)(I + row);
    float* prow = g_partial + (size_t)blockIdx.x * LL;

    float4 ibuf[8];
#pragma unroll
    for (int j = 0; j < 8; ++j) ibuf[j] = Ir[j];

    float v = 0.0f;
    const float kk = 0.2f;

    for (int tile = 0; tile < 256; ++tile) {
#pragma unroll
        for (int u = 0; u < 8; ++u) {
            const int g = tile * 8 + u;          // float4 group index (4 timesteps)
            float4 iv = ibuf[u];
            if (g + 8 < 2048) ibuf[u] = Ir[g + 8];   // deep prefetch

            float vp0 = fmaf(kk, iv.x - v, v);
            float s0  = (vp0 >= 1.0f) ? 1.0f : 0.0f;
            v         = (vp0 >= 1.0f) ? 0.0f : vp0;
            float vn0 = v;

            float vp1 = fmaf(kk, iv.y - v, v);
            float s1  = (vp1 >= 1.0f) ? 1.0f : 0.0f;
            v         = (vp1 >= 1.0f) ? 0.0f : vp1;
            float vn1 = v;

            float vp2 = fmaf(kk, iv.z - v, v);
            float s2  = (vp2 >= 1.0f) ? 1.0f : 0.0f;
            v         = (vp2 >= 1.0f) ? 0.0f : vp2;
            float vn2 = v;

            float vp3 = fmaf(kk, iv.w - v, v);
            float s3  = (vp3 >= 1.0f) ? 1.0f : 0.0f;
            v         = (vp3 >= 1.0f) ? 0.0f : vp3;
            float vn3 = v;

            const int sa = tid * 36 + u * 4;
            *(float4*)&tvp[sa] = make_float4(vp0, vp1, vp2, vp3);
            *(float4*)&tvn[sa] = make_float4(vn0, vn1, vn2, vn3);
            *(float4*)&tsp[sa] = make_float4(s0, s1, s2, s3);
        }
        __syncthreads();

        const int t0 = tile * 32;
        // Cooperative coalesced stores: 64 rows x 32 cols per array.
        // warp = 4 rows x 8 float4 -> 4x 128B lines per STG.128 warp-op.
#pragma unroll
        for (int r = 0; r < 8; ++r) {
            int idx = r * 64 + tid;          // 0..511
            int rw  = idx >> 3;
            int c4  = (idx & 7) * 4;
            size_t gaddr = ((size_t)(b * FF + h * 64 + rw)) * LL + t0 + c4;
            int saddr = rw * 36 + c4;
            *(float4*)(vpre_out + gaddr) = *(float4*)&tvp[saddr];
            *(float4*)(v_out    + gaddr) = *(float4*)&tvn[saddr];
            *(float4*)(s_out    + gaddr) = *(float4*)&tsp[saddr];
        }
        // Partial logits: column max of v_pre over the 64 filters in this half.
        {
            int col = tid & 31, q = tid >> 5;   // q in {0,1}: rows q*32..q*32+31
            float m = -1e30f;
#pragma unroll
            for (int r = 0; r < 32; ++r)
                m = fmaxf(m, tvp[(q * 32 + r) * 36 + col]);
            pmax[q * 32 + col] = m;
        }
        __syncthreads();
        if (tid < 32) prow[t0 + tid] = fmaxf(pmax[tid], pmax[tid + 32]);
    }
}

// ---------------------------------------------------------------------------
// Kernel 3: combine the two filter-halves into final logits and subtract theta.
// ---------------------------------------------------------------------------
__global__ void logits_kernel(float* __restrict__ logits)
{
    int i = blockIdx.x * blockDim.x + threadIdx.x;   // 0..BB*LL-1
    int b = i >> 13;
    int l = i & (LL - 1);
    float m = fmaxf(g_partial[(size_t)(2 * b) * LL + l],
                    g_partial[(size_t)(2 * b + 1) * LL + l]);
    logits[i] = m - 1.0f;
}

extern "C" void kernel_launch(void* const* d_in, const int* in_sizes, int n_in,
                              void* d_out, int out_size)
{
    const float* x    = (const float*)d_in[0];
    const float* W    = (const float*)d_in[1];
    const float* bias = (const float*)d_in[2];
    float* out = (float*)d_out;

    const size_t N = (size_t)BB * FF * LL;   // 67,108,864
    float* I    = out;
    float* vpre = out + N;
    float* vv   = out + 2 * N;
    float* ss   = out + 3 * N;
    float* lg   = out + 4 * N;

    conv_kernel<<<dim3(LL / 512, BB), 128>>>(x, W, bias, I);
    lif_kernel<<<128, 64>>>(I, vpre, vv, ss);
    logits_kernel<<<(BB * LL) / 256, 256>>>(lg);
}

// round 2
// speedup vs baseline: 1.1950x; 1.1950x over previous
#include <cuda_runtime.h>

#define BB 64
#define FF 128
#define LL 8192
#define KK 16
#define TILE 32
#define NTILES (LL / TILE)        // 256
#define RSTRIDE 36                // padded row stride (floats), 16B aligned
#define TSZ (64 * RSTRIDE)        // 2304 floats per tile buffer

// per-(batch,half) partial logits max: [128 blocks][8192]
__device__ float g_partial[128 * LL];

// ---------------------------------------------------------------------------
// Conv tile: producers compute I[f, t0..t0+31] for 64 filters.
// idx = f*8 + tq: warp covers 4 rows x 8 quads -> 4x128B lines per STG.128.
// ---------------------------------------------------------------------------
__device__ __forceinline__ void conv_tile(
    int tile, int ptid, const float* __restrict__ sw,
    const float* __restrict__ sb, const float* __restrict__ xs,
    float* __restrict__ ibuf, float* __restrict__ I_out, int frow0)
{
    for (int idx = ptid; idx < 512; idx += 192) {
        const int f = idx >> 3, tq = idx & 7;
        float wr[16];
        *(float4*)&wr[0]  = *(const float4*)(sw + f * KK);
        *(float4*)&wr[4]  = *(const float4*)(sw + f * KK + 4);
        *(float4*)&wr[8]  = *(const float4*)(sw + f * KK + 8);
        *(float4*)&wr[12] = *(const float4*)(sw + f * KK + 12);
        float xr[19];
#pragma unroll
        for (int j = 0; j < 19; ++j) xr[j] = xs[tq * 4 + j];
        const float bv = sb[f];
        float a0 = bv, a1 = bv, a2 = bv, a3 = bv;
#pragma unroll
        for (int k = 0; k < KK; ++k) {
            a0 = fmaf(wr[k], xr[k],     a0);
            a1 = fmaf(wr[k], xr[k + 1], a1);
            a2 = fmaf(wr[k], xr[k + 2], a2);
            a3 = fmaf(wr[k], xr[k + 3], a3);
        }
        float4 r = make_float4(a0, a1, a2, a3);
        *(float4*)&ibuf[f * RSTRIDE + tq * 4] = r;
        *(float4*)(I_out + (size_t)(frow0 + f) * LL + (size_t)tile * TILE + tq * 4) = r;
    }
}

// ---------------------------------------------------------------------------
// Fused conv + LIF + transposed coalesced stores + fused partial logits.
// Grid 128 = (batch, filter-half). 256 threads:
//   threads 0-63:   LIF chain (one filter each), consume SMEM I tiles,
//                   emit v_pre/v/s tiles to SMEM, column-max -> g_partial.
//   threads 64-255: producers — conv for tile T+1 into double-buffered SMEM
//                   (+ coalesced STG of I), flush result tiles of T-1.
// ---------------------------------------------------------------------------
__global__ __launch_bounds__(256, 1) void snn_fused_kernel(
    const float* __restrict__ x, const float* __restrict__ W,
    const float* __restrict__ bias, float* __restrict__ I_out,
    float* __restrict__ vpre_out, float* __restrict__ v_out,
    float* __restrict__ s_out)
{
    extern __shared__ float sm[];
    float* Ibuf = sm;               // 2*TSZ
    float* tvp  = sm + 2 * TSZ;     // 2*TSZ
    float* tvn  = sm + 4 * TSZ;     // 2*TSZ
    float* tsp  = sm + 6 * TSZ;     // 2*TSZ
    float* sw   = sm + 8 * TSZ;     // 1024
    float* sb   = sw + 1024;        // 64
    float* xs   = sb + 64;          // 64 (47 used)
    float* pmax = xs + 64;          // 64

    const int tid   = threadIdx.x;
    const int b     = blockIdx.x >> 1;
    const int h     = blockIdx.x & 1;
    const int frow0 = b * FF + h * 64;
    const float* __restrict__ xb = x + (size_t)b * LL;

    const float KI = 0.2f;                 // DT/TAU
    const float A  = 1.0f - 0.2f;          // decay

    // ---- prologue: producers stage weights, xs(tile0), conv tile 0 ----
    if (tid >= 64) {
        const int ptid = tid - 64;
        for (int i = ptid; i < 64 * KK; i += 192) sw[i] = W[(h * 64) * KK + i];
        if (ptid < 64) sb[ptid] = bias[h * 64 + ptid];
        if (ptid < 47) { int g = ptid - 15; xs[ptid] = (g >= 0) ? xb[g] : 0.0f; }
        asm volatile("bar.sync 1, 192;" ::: "memory");
        conv_tile(0, ptid, sw, sb, xs, Ibuf, I_out, frow0);
    }
    __syncthreads();

    float v = 0.0f;
    float* __restrict__ prow = g_partial + (size_t)blockIdx.x * LL;

    for (int tile = 0; tile < NTILES; ++tile) {
        const int buf = tile & 1;
        if (tid < 64) {
            // ---------------- chain warps ----------------
            const float* ib = Ibuf + buf * TSZ + tid * RSTRIDE;
            float* wp = tvp + buf * TSZ + tid * RSTRIDE;
            float* wn = tvn + buf * TSZ + tid * RSTRIDE;
            float* ws = tsp + buf * TSZ + tid * RSTRIDE;

            float4 cur = *(const float4*)ib;
#pragma unroll
            for (int u = 0; u < 8; ++u) {
                float4 nxt = (u < 7) ? *(const float4*)(ib + (u + 1) * 4) : cur;
                const float c0 = KI * cur.x, c1 = KI * cur.y;
                const float c2 = KI * cur.z, c3 = KI * cur.w;

                float vp0 = fmaf(v, A, c0);
                float s0  = (vp0 >= 1.0f) ? 1.0f : 0.0f;
                v         = (vp0 >= 1.0f) ? 0.0f : vp0;
                float vn0 = v;
                float vp1 = fmaf(v, A, c1);
                float s1  = (vp1 >= 1.0f) ? 1.0f : 0.0f;
                v         = (vp1 >= 1.0f) ? 0.0f : vp1;
                float vn1 = v;
                float vp2 = fmaf(v, A, c2);
                float s2  = (vp2 >= 1.0f) ? 1.0f : 0.0f;
                v         = (vp2 >= 1.0f) ? 0.0f : vp2;
                float vn2 = v;
                float vp3 = fmaf(v, A, c3);
                float s3  = (vp3 >= 1.0f) ? 1.0f : 0.0f;
                v         = (vp3 >= 1.0f) ? 0.0f : vp3;
                float vn3 = v;

                *(float4*)(wp + u * 4) = make_float4(vp0, vp1, vp2, vp3);
                *(float4*)(wn + u * 4) = make_float4(vn0, vn1, vn2, vn3);
                *(float4*)(ws + u * 4) = make_float4(s0, s1, s2, s3);
                cur = nxt;
            }
            asm volatile("bar.sync 2, 64;" ::: "memory");
            // column max of v_pre over 64 filters (this half)
            {
                const int col = tid & 31, q = tid >> 5;
                const float* tp = tvp + buf * TSZ;
                float m = -1e30f;
#pragma unroll
                for (int r = 0; r < 32; ++r)
                    m = fmaxf(m, tp[(q * 32 + r) * RSTRIDE + col]);
                pmax[tid] = m;
            }
            asm volatile("bar.sync 2, 64;" ::: "memory");
            if (tid < 32)
                prow[tile * TILE + tid] = fmaxf(pmax[tid], pmax[tid + 32]);
        } else {
            // ---------------- producer warps ----------------
            const int ptid = tid - 64;
            if (tile + 1 < NTILES) {
                if (ptid < 47) {
                    int g = (tile + 1) * TILE - 15 + ptid;
                    xs[ptid] = xb[g];            // g >= 17 here, always valid
                }
                asm volatile("bar.sync 1, 192;" ::: "memory");
                conv_tile(tile + 1, ptid, sw, sb, xs,
                          Ibuf + ((tile + 1) & 1) * TSZ, I_out, frow0);
            }
            if (tile >= 1) {
                const int fb = (tile - 1) & 1;
                const size_t tg = (size_t)(tile - 1) * TILE;
                for (int idx = ptid; idx < 512; idx += 192) {
                    const int f = idx >> 3, tq = idx & 7;
                    const int sa = fb * TSZ + f * RSTRIDE + tq * 4;
                    const size_t ga = (size_t)(frow0 + f) * LL + tg + tq * 4;
                    *(float4*)(vpre_out + ga) = *(float4*)&tvp[sa];
                    *(float4*)(v_out    + ga) = *(float4*)&tvn[sa];
                    *(float4*)(s_out    + ga) = *(float4*)&tsp[sa];
                }
            }
        }
        __syncthreads();
    }

    // ---- epilogue: flush last result tile (tile 255, buffer 1) ----
    if (tid >= 64) {
        const int ptid = tid - 64;
        const int fb = (NTILES - 1) & 1;
        const size_t tg = (size_t)(NTILES - 1) * TILE;
        for (int idx = ptid; idx < 512; idx += 192) {
            const int f = idx >> 3, tq = idx & 7;
            const int sa = fb * TSZ + f * RSTRIDE + tq * 4;
            const size_t ga = (size_t)(frow0 + f) * LL + tg + tq * 4;
            *(float4*)(vpre_out + ga) = *(float4*)&tvp[sa];
            *(float4*)(v_out    + ga) = *(float4*)&tvn[sa];
            *(float4*)(s_out    + ga) = *(float4*)&tsp[sa];
        }
    }
}

// ---------------------------------------------------------------------------
// Combine the two filter-half partial maxes into final logits, subtract theta.
// ---------------------------------------------------------------------------
__global__ void logits_kernel(float* __restrict__ logits)
{
    int i = blockIdx.x * blockDim.x + threadIdx.x;   // 0..BB*LL-1
    int b = i >> 13;
    int l = i & (LL - 1);
    float m = fmaxf(g_partial[(size_t)(2 * b) * LL + l],
                    g_partial[(size_t)(2 * b + 1) * LL + l]);
    logits[i] = m - 1.0f;
}

extern "C" void kernel_launch(void* const* d_in, const int* in_sizes, int n_in,
                              void* d_out, int out_size)
{
    const float* x    = (const float*)d_in[0];
    const float* W    = (const float*)d_in[1];
    const float* bias = (const float*)d_in[2];
    float* out = (float*)d_out;

    const size_t N = (size_t)BB * FF * LL;   // 67,108,864
    float* I    = out;
    float* vpre = out + N;
    float* vv   = out + 2 * N;
    float* ss   = out + 3 * N;
    float* lg   = out + 4 * N;

    const int smem_bytes = (8 * TSZ + 1024 + 64 + 64 + 64) * sizeof(float); // 78592
    cudaFuncSetAttribute(snn_fused_kernel,
                         cudaFuncAttributeMaxDynamicSharedMemorySize, smem_bytes);

    snn_fused_kernel<<<128, 256, smem_bytes>>>(x, W, bias, I, vpre, vv, ss);
    logits_kernel<<<(BB * LL) / 256, 256>>>(lg);
}

// round 4
// speedup vs baseline: 2.5985x; 2.1745x over previous
#include <cuda_runtime.h>

#define BB 64
#define FF 128
#define LL 8192
#define KK 16
#define TILE 64
#define NTILES (LL / TILE)      // 128
#define RS 68                   // padded SMEM row stride (floats)
#define TSZ (64 * RS)           // 4352 floats per tile buffer

typedef unsigned long long u64;

__device__ float  g_partial[128 * LL];   // per-(batch,half) partial logits max
__device__ float2 g_wpack[FF * KK];      // duplicated weight pairs (w,w)

__device__ __forceinline__ u64 fma2(u64 a, u64 b, u64 c) {
    u64 d;
    asm("fma.rn.f32x2 %0, %1, %2, %3;" : "=l"(d) : "l"(a), "l"(b), "l"(c));
    return d;
}
__device__ __forceinline__ u64 pack2(float lo, float hi) {
    u64 d; asm("mov.b64 %0, {%1, %2};" : "=l"(d) : "f"(lo), "f"(hi)); return d;
}
__device__ __forceinline__ void unpack2(u64 v, float& lo, float& hi) {
    asm("mov.b64 {%0, %1}, %2;" : "=f"(lo), "=f"(hi) : "l"(v));
}
__device__ __forceinline__ void stcs4(float* p, float4 v) {
    asm volatile("st.global.cs.v4.f32 [%0], {%1,%2,%3,%4};"
                 :: "l"(p), "f"(v.x), "f"(v.y), "f"(v.z), "f"(v.w) : "memory");
}
__device__ __forceinline__ float4 max4(float4 a, float4 b) {
    return make_float4(fmaxf(a.x, b.x), fmaxf(a.y, b.y),
                       fmaxf(a.z, b.z), fmaxf(a.w, b.w));
}

// ---------------------------------------------------------------------------
__global__ void pack_kernel(const float* __restrict__ W) {
    int i = blockIdx.x * blockDim.x + threadIdx.x;   // 0..2047
    float w = W[i];
    g_wpack[i] = make_float2(w, w);
}

// ---------------------------------------------------------------------------
// conv: one quad half (8 quads) for fixed filter f. Packed f32x2 FMAs.
// xs[p]  = x[tile*64 - 15 + p]; xsh[q] = xs[q+1] (odd-parity pairs).
// ---------------------------------------------------------------------------
__device__ __forceinline__ void conv_do(
    int qh, const float* __restrict__ xs, const float* __restrict__ xsh,
    const u64* __restrict__ w2, u64 bias2, float* __restrict__ irow)
{
#pragma unroll
    for (int j = 0; j < 8; ++j) {
        const int lt4 = qh * 32 + 4 * j;     // even
        u64 P[18];
#pragma unroll
        for (int m = 0; m < 18; ++m) {
            int base = lt4 + m;              // parity == m parity
            P[m] = (m & 1) ? *(const u64*)(xsh + (base - 1))
                           : *(const u64*)(xs + base);
        }
        u64 a01 = bias2, a23 = bias2;
#pragma unroll
        for (int k = 0; k < KK; ++k) {
            a01 = fma2(w2[k], P[k],     a01);
            a23 = fma2(w2[k], P[k + 2], a23);
        }
        float o0, o1, o2, o3;
        unpack2(a01, o0, o1);
        unpack2(a23, o2, o3);
        *(float4*)(irow + lt4) = make_float4(o0, o1, o2, o3);
    }
}

// ---------------------------------------------------------------------------
// Fused conv + LIF + coalesced streaming stores + fused logits partial max.
// Grid 128 = (batch, filter-half), 256 threads:
//   tid   0- 63 : chain warps  — LIF recurrence, write v_pre tiles to SMEM
//   tid  64-191 : conv warps   — f32x2 conv of tile T+1 into SMEM (dbl-buf)
//   tid 192-255 : flush warps  — STG I(T); STG v_pre/v/s(T-1) with derive;
//                                running column-max -> g_partial
// ---------------------------------------------------------------------------
__global__ __launch_bounds__(256, 1) void snn_fused(
    const float* __restrict__ x, const float* __restrict__ bias,
    float* __restrict__ I_out, float* __restrict__ vpre_out,
    float* __restrict__ v_out, float* __restrict__ s_out)
{
    extern __shared__ float sm[];
    float* Ibuf = sm;                 // 2*TSZ
    float* tvp  = sm + 2 * TSZ;       // 2*TSZ
    float* xs   = sm + 4 * TSZ;       // 84
    float* xsh  = xs + 84;            // 84
    float* red  = xsh + 84;           // 256

    const int tid   = threadIdx.x;
    const int b     = blockIdx.x >> 1;
    const int h     = blockIdx.x & 1;
    const int frow0 = b * FF + h * 64;          // OUTPUT row base (batch-dep)
    const float* __restrict__ xb = x + (size_t)b * LL;
    float* __restrict__ prow = g_partial + (size_t)blockIdx.x * LL;

    // conv-thread persistent state (filter index is batch-INDEPENDENT)
    u64 w2[KK];
    u64 bias2 = 0;
    int f_loc = 0, qh = 0;
    if (tid >= 64 && tid < 192) {
        const int p = tid - 64;
        f_loc = p >> 1; qh = p & 1;
        const int fflt = h * 64 + f_loc;        // filter index 0..127
#pragma unroll
        for (int k = 0; k < KK; ++k)
            w2[k] = *((const u64*)g_wpack + fflt * KK + k);
        const float bv = bias[fflt];
        bias2 = pack2(bv, bv);
    }

    // ---- prologue: stage xs(tile0), conv tile0 -> Ibuf[0] ----
    if (tid >= 64 && tid < 192) {
        const int p = tid - 64;
        if (p < 79) {
            int g = p - 15;
            float val = (g >= 0) ? xb[g] : 0.0f;
            xs[p] = val;
            if (p >= 1) xsh[p - 1] = val;
        }
        asm volatile("bar.sync 1, 128;" ::: "memory");
        conv_do(qh, xs, xsh, w2, bias2, Ibuf + f_loc * RS);
    }
    __syncthreads();

    float vchain = 0.0f;

    for (int T = 0; T < NTILES; ++T) {
        const int buf = T & 1;
        if (tid < 64) {
            // ---------------- chain ----------------
            const float* ir = Ibuf + buf * TSZ + tid * RS;
            float* vr = tvp + buf * TSZ + tid * RS;
            float4 cur = *(const float4*)ir;
#pragma unroll
            for (int q = 0; q < 16; ++q) {
                float4 nxt = (q < 15) ? *(const float4*)(ir + 4 * (q + 1)) : cur;
                const float c0 = 0.2f * cur.x, c1 = 0.2f * cur.y;
                const float c2 = 0.2f * cur.z, c3 = 0.2f * cur.w;
                float vp0 = fmaf(vchain, 0.8f, c0);
                vchain = (vp0 >= 1.0f) ? 0.0f : vp0;
                float vp1 = fmaf(vchain, 0.8f, c1);
                vchain = (vp1 >= 1.0f) ? 0.0f : vp1;
                float vp2 = fmaf(vchain, 0.8f, c2);
                vchain = (vp2 >= 1.0f) ? 0.0f : vp2;
                float vp3 = fmaf(vchain, 0.8f, c3);
                vchain = (vp3 >= 1.0f) ? 0.0f : vp3;
                *(float4*)(vr + 4 * q) = make_float4(vp0, vp1, vp2, vp3);
                cur = nxt;
            }
        } else if (tid < 192) {
            // ---------------- conv ----------------
            const int p = tid - 64;
            if (T + 1 < NTILES) {
                if (p < 79) {
                    int g = (T + 1) * TILE - 15 + p;
                    float val = xb[g];           // g >= 49, always valid
                    xs[p] = val;
                    if (p >= 1) xsh[p - 1] = val;
                }
                asm volatile("bar.sync 1, 128;" ::: "memory");
                conv_do(qh, xs, xsh, w2, bias2,
                        Ibuf + ((T + 1) & 1) * TSZ + f_loc * RS);
            }
        } else {
            // ---------------- flush ----------------
            const int ft = tid - 192;
            const int r0 = ft >> 4, tq = ft & 15;
            const float* ib  = Ibuf + buf * TSZ;
            const float* vpb = tvp + (buf ^ 1) * TSZ;
            const size_t tcol = (size_t)T * TILE + tq * 4;
            const size_t pcol = (size_t)(T - 1) * TILE + tq * 4;
            float4 mx = make_float4(-1e30f, -1e30f, -1e30f, -1e30f);
#pragma unroll
            for (int i = 0; i < 16; ++i) {
                const int r = r0 + 4 * i;
                const size_t grow = (size_t)(frow0 + r) * LL;
                float4 iq = *(const float4*)(ib + r * RS + tq * 4);
                stcs4(I_out + grow + tcol, iq);
                if (T >= 1) {
                    float4 vq = *(const float4*)(vpb + r * RS + tq * 4);
                    float4 sq, vn;
                    sq.x = (vq.x >= 1.0f) ? 1.0f : 0.0f;
                    sq.y = (vq.y >= 1.0f) ? 1.0f : 0.0f;
                    sq.z = (vq.z >= 1.0f) ? 1.0f : 0.0f;
                    sq.w = (vq.w >= 1.0f) ? 1.0f : 0.0f;
                    vn.x = (vq.x >= 1.0f) ? 0.0f : vq.x;
                    vn.y = (vq.y >= 1.0f) ? 0.0f : vq.y;
                    vn.z = (vq.z >= 1.0f) ? 0.0f : vq.z;
                    vn.w = (vq.w >= 1.0f) ? 0.0f : vq.w;
                    stcs4(vpre_out + grow + pcol, vq);
                    stcs4(v_out    + grow + pcol, vn);
                    stcs4(s_out    + grow + pcol, sq);
                    mx = max4(mx, vq);
                }
            }
            if (T >= 1) {
                *(float4*)(red + ft * 4) = mx;
                asm volatile("bar.sync 3, 64;" ::: "memory");
                if (ft < 16) {
                    float4 a  = *(float4*)(red + ft * 4);
                    float4 b4 = *(float4*)(red + (16 + ft) * 4);
                    float4 c4 = *(float4*)(red + (32 + ft) * 4);
                    float4 d4 = *(float4*)(red + (48 + ft) * 4);
                    a = max4(max4(a, b4), max4(c4, d4));
                    *(float4*)(prow + (size_t)(T - 1) * TILE + ft * 4) = a;
                }
            }
        }
        __syncthreads();
    }

    // ---- epilogue: flush v_pre/v/s + logits of tile 127 (buffer 1) ----
    if (tid >= 192) {
        const int ft = tid - 192;
        const int r0 = ft >> 4, tq = ft & 15;
        const float* vpb = tvp + ((NTILES - 1) & 1) * TSZ;
        const size_t pcol = (size_t)(NTILES - 1) * TILE + tq * 4;
        float4 mx = make_float4(-1e30f, -1e30f, -1e30f, -1e30f);
#pragma unroll
        for (int i = 0; i < 16; ++i) {
            const int r = r0 + 4 * i;
            const size_t grow = (size_t)(frow0 + r) * LL;
            float4 vq = *(const float4*)(vpb + r * RS + tq * 4);
            float4 sq, vn;
            sq.x = (vq.x >= 1.0f) ? 1.0f : 0.0f;
            sq.y = (vq.y >= 1.0f) ? 1.0f : 0.0f;
            sq.z = (vq.z >= 1.0f) ? 1.0f : 0.0f;
            sq.w = (vq.w >= 1.0f) ? 1.0f : 0.0f;
            vn.x = (vq.x >= 1.0f) ? 0.0f : vq.x;
            vn.y = (vq.y >= 1.0f) ? 0.0f : vq.y;
            vn.z = (vq.z >= 1.0f) ? 0.0f : vq.z;
            vn.w = (vq.w >= 1.0f) ? 0.0f : vq.w;
            stcs4(vpre_out + grow + pcol, vq);
            stcs4(v_out    + grow + pcol, vn);
            stcs4(s_out    + grow + pcol, sq);
            mx = max4(mx, vq);
        }
        *(float4*)(red + ft * 4) = mx;
        asm volatile("bar.sync 3, 64;" ::: "memory");
        if (ft < 16) {
            float4 a  = *(float4*)(red + ft * 4);
            float4 b4 = *(float4*)(red + (16 + ft) * 4);
            float4 c4 = *(float4*)(red + (32 + ft) * 4);
            float4 d4 = *(float4*)(red + (48 + ft) * 4);
            a = max4(max4(a, b4), max4(c4, d4));
            *(float4*)(prow + (size_t)(NTILES - 1) * TILE + ft * 4) = a;
        }
    }
}

// ---------------------------------------------------------------------------
// Combine the two filter-half partial maxes into logits for 32 batches.
// ---------------------------------------------------------------------------
__global__ void logits_kernel(float* __restrict__ logits, int b0)
{
    int i = blockIdx.x * blockDim.x + threadIdx.x;   // 0 .. 32*LL-1
    int b = b0 + (i >> 13);
    int l = i & (LL - 1);
    float m = fmaxf(g_partial[(size_t)(2 * b) * LL + l],
                    g_partial[(size_t)(2 * b + 1) * LL + l]);
    logits[(size_t)b * LL + l] = m - 1.0f;
}

extern "C" void kernel_launch(void* const* d_in, const int* in_sizes, int n_in,
                              void* d_out, int out_size)
{
    const float* x    = (const float*)d_in[0];
    const float* W    = (const float*)d_in[1];
    const float* bias = (const float*)d_in[2];
    float* out = (float*)d_out;

    const size_t N = (size_t)BB * FF * LL;   // 67,108,864
    float* I    = out;
    float* vpre = out + N;
    float* vv   = out + 2 * N;
    float* ss   = out + 3 * N;
    float* lg   = out + 4 * N;

    const int smem_bytes = (4 * TSZ + 84 + 84 + 256) * sizeof(float); // ~71.3KB
    cudaFuncSetAttribute(snn_fused,
                         cudaFuncAttributeMaxDynamicSharedMemorySize, smem_bytes);

    pack_kernel<<<FF * KK / 256, 256>>>(W);
    snn_fused<<<128, 256, smem_bytes>>>(x, bias, I, vpre, vv, ss);
    logits_kernel<<<(32 * LL) / 256, 256>>>(lg, 0);
    logits_kernel<<<(32 * LL) / 256, 256>>>(lg, 32);
}

// round 5
// speedup vs baseline: 2.6653x; 1.0257x over previous
#include <cuda_runtime.h>

#define BB 64
#define FF 128
#define LL 8192
#define KK 16
#define TILE 64
#define NTILES (LL / TILE)      // 128
#define RS 68                   // padded SMEM row stride (floats)
#define TSZ (64 * RS)           // 4352 floats per tile buffer

typedef unsigned long long u64;

__device__ float g_partial[128 * LL];   // per-(batch,half) partial logits max

__device__ __forceinline__ u64 fma2(u64 a, u64 b, u64 c) {
    u64 d;
    asm("fma.rn.f32x2 %0, %1, %2, %3;" : "=l"(d) : "l"(a), "l"(b), "l"(c));
    return d;
}
__device__ __forceinline__ u64 pack2(float lo, float hi) {
    u64 d; asm("mov.b64 %0, {%1, %2};" : "=l"(d) : "f"(lo), "f"(hi)); return d;
}
__device__ __forceinline__ void unpack2(u64 v, float& lo, float& hi) {
    asm("mov.b64 {%0, %1}, %2;" : "=f"(lo), "=f"(hi) : "l"(v));
}
__device__ __forceinline__ void stcs4(float* p, float4 v) {
    asm volatile("st.global.cs.v4.f32 [%0], {%1,%2,%3,%4};"
                 :: "l"(p), "f"(v.x), "f"(v.y), "f"(v.z), "f"(v.w) : "memory");
}
__device__ __forceinline__ float4 max4(float4 a, float4 b) {
    return make_float4(fmaxf(a.x, b.x), fmaxf(a.y, b.y),
                       fmaxf(a.z, b.z), fmaxf(a.w, b.w));
}

// ---------------------------------------------------------------------------
// conv: one quad half (8 quads) for fixed filter f. Packed f32x2 FMAs.
// xs[p]  = x[tile*64 - 15 + p]; xsh[q] = xs[q+1] (odd-parity pairs).
// ---------------------------------------------------------------------------
__device__ __forceinline__ void conv_do(
    int qh, const float* __restrict__ xs, const float* __restrict__ xsh,
    const u64* __restrict__ w2, u64 bias2, float* __restrict__ irow)
{
#pragma unroll
    for (int j = 0; j < 8; ++j) {
        const int lt4 = qh * 32 + 4 * j;     // even
        u64 P[18];
#pragma unroll
        for (int m = 0; m < 18; ++m) {
            int base = lt4 + m;              // parity == m parity
            P[m] = (m & 1) ? *(const u64*)(xsh + (base - 1))
                           : *(const u64*)(xs + base);
        }
        u64 a01 = bias2, a23 = bias2;
#pragma unroll
        for (int k = 0; k < KK; ++k) {
            a01 = fma2(w2[k], P[k],     a01);
            a23 = fma2(w2[k], P[k + 2], a23);
        }
        float o0, o1, o2, o3;
        unpack2(a01, o0, o1);
        unpack2(a23, o2, o3);
        *(float4*)(irow + lt4) = make_float4(o0, o1, o2, o3);
    }
}

// ---------------------------------------------------------------------------
// Fused conv + LIF + coalesced streaming stores + fused logits partial max.
// Grid 128 = (batch, filter-half), 256 threads:
//   tid   0- 63 : chain warps  — LIF recurrence, write v_pre tiles to SMEM
//   tid  64-191 : conv warps   — f32x2 conv of tile T+1 into SMEM (dbl-buf)
//   tid 192-255 : flush warps  — STG I(T); STG v_pre/v/s(T-1) with derive;
//                                running column-max -> g_partial
// ---------------------------------------------------------------------------
__global__ __launch_bounds__(256, 1) void snn_fused(
    const float* __restrict__ x, const float* __restrict__ W,
    const float* __restrict__ bias,
    float* __restrict__ I_out, float* __restrict__ vpre_out,
    float* __restrict__ v_out, float* __restrict__ s_out)
{
    extern __shared__ float sm[];
    float* Ibuf = sm;                 // 2*TSZ
    float* tvp  = sm + 2 * TSZ;       // 2*TSZ
    float* xs   = sm + 4 * TSZ;       // 84
    float* xsh  = xs + 84;            // 84
    float* red  = xsh + 84;           // 256

    const int tid   = threadIdx.x;
    const int b     = blockIdx.x >> 1;
    const int h     = blockIdx.x & 1;
    const int frow0 = b * FF + h * 64;          // OUTPUT row base (batch-dep)
    const float* __restrict__ xb = x + (size_t)b * LL;
    float* __restrict__ prow = g_partial + (size_t)blockIdx.x * LL;

    // conv-thread persistent state (filter index is batch-INDEPENDENT)
    u64 w2[KK];
    u64 bias2 = 0;
    int f_loc = 0, qh = 0;
    if (tid >= 64 && tid < 192) {
        const int p = tid - 64;
        f_loc = p >> 1; qh = p & 1;
        const int fflt = h * 64 + f_loc;        // filter index 0..127
#pragma unroll
        for (int k = 0; k < KK; ++k) {
            const float w = W[fflt * KK + k];
            w2[k] = pack2(w, w);
        }
        const float bv = bias[fflt];
        bias2 = pack2(bv, bv);
    }

    // ---- prologue: stage xs(tile0), conv tile0 -> Ibuf[0] ----
    if (tid >= 64 && tid < 192) {
        const int p = tid - 64;
        if (p < 79) {
            int g = p - 15;
            float val = (g >= 0) ? xb[g] : 0.0f;
            xs[p] = val;
            if (p >= 1) xsh[p - 1] = val;
        }
        asm volatile("bar.sync 1, 128;" ::: "memory");
        conv_do(qh, xs, xsh, w2, bias2, Ibuf + f_loc * RS);
    }
    __syncthreads();

    float vchain = 0.0f;

    for (int T = 0; T < NTILES; ++T) {
        const int buf = T & 1;
        if (tid < 64) {
            // ---------------- chain ----------------
            const float* ir = Ibuf + buf * TSZ + tid * RS;
            float* vr = tvp + buf * TSZ + tid * RS;
            float4 cur = *(const float4*)ir;
#pragma unroll
            for (int q = 0; q < 16; ++q) {
                float4 nxt = (q < 15) ? *(const float4*)(ir + 4 * (q + 1)) : cur;
                const float c0 = 0.2f * cur.x, c1 = 0.2f * cur.y;
                const float c2 = 0.2f * cur.z, c3 = 0.2f * cur.w;
                float vp0 = fmaf(vchain, 0.8f, c0);
                vchain = (vp0 >= 1.0f) ? 0.0f : vp0;
                float vp1 = fmaf(vchain, 0.8f, c1);
                vchain = (vp1 >= 1.0f) ? 0.0f : vp1;
                float vp2 = fmaf(vchain, 0.8f, c2);
                vchain = (vp2 >= 1.0f) ? 0.0f : vp2;
                float vp3 = fmaf(vchain, 0.8f, c3);
                vchain = (vp3 >= 1.0f) ? 0.0f : vp3;
                *(float4*)(vr + 4 * q) = make_float4(vp0, vp1, vp2, vp3);
                cur = nxt;
            }
        } else if (tid < 192) {
            // ---------------- conv ----------------
            const int p = tid - 64;
            if (T + 1 < NTILES) {
                if (p < 79) {
                    int g = (T + 1) * TILE - 15 + p;
                    float val = xb[g];           // g >= 49, always valid
                    xs[p] = val;
                    if (p >= 1) xsh[p - 1] = val;
                }
                asm volatile("bar.sync 1, 128;" ::: "memory");
                conv_do(qh, xs, xsh, w2, bias2,
                        Ibuf + ((T + 1) & 1) * TSZ + f_loc * RS);
            }
        } else {
            // ---------------- flush ----------------
            const int ft = tid - 192;
            const int r0 = ft >> 4, tq = ft & 15;
            const float* ib  = Ibuf + buf * TSZ;
            const float* vpb = tvp + (buf ^ 1) * TSZ;
            const size_t tcol = (size_t)T * TILE + tq * 4;
            const size_t pcol = (size_t)(T - 1) * TILE + tq * 4;
            float4 mx = make_float4(-1e30f, -1e30f, -1e30f, -1e30f);
#pragma unroll
            for (int i = 0; i < 16; ++i) {
                const int r = r0 + 4 * i;
                const size_t grow = (size_t)(frow0 + r) * LL;
                float4 iq = *(const float4*)(ib + r * RS + tq * 4);
                stcs4(I_out + grow + tcol, iq);
                if (T >= 1) {
                    float4 vq = *(const float4*)(vpb + r * RS + tq * 4);
                    float4 sq, vn;
                    sq.x = (vq.x >= 1.0f) ? 1.0f : 0.0f;
                    sq.y = (vq.y >= 1.0f) ? 1.0f : 0.0f;
                    sq.z = (vq.z >= 1.0f) ? 1.0f : 0.0f;
                    sq.w = (vq.w >= 1.0f) ? 1.0f : 0.0f;
                    vn.x = (vq.x >= 1.0f) ? 0.0f : vq.x;
                    vn.y = (vq.y >= 1.0f) ? 0.0f : vq.y;
                    vn.z = (vq.z >= 1.0f) ? 0.0f : vq.z;
                    vn.w = (vq.w >= 1.0f) ? 0.0f : vq.w;
                    stcs4(vpre_out + grow + pcol, vq);
                    stcs4(v_out    + grow + pcol, vn);
                    stcs4(s_out    + grow + pcol, sq);
                    mx = max4(mx, vq);
                }
            }
            if (T >= 1) {
                *(float4*)(red + ft * 4) = mx;
                asm volatile("bar.sync 3, 64;" ::: "memory");
                if (ft < 16) {
                    float4 a  = *(float4*)(red + ft * 4);
                    float4 b4 = *(float4*)(red + (16 + ft) * 4);
                    float4 c4 = *(float4*)(red + (32 + ft) * 4);
                    float4 d4 = *(float4*)(red + (48 + ft) * 4);
                    a = max4(max4(a, b4), max4(c4, d4));
                    *(float4*)(prow + (size_t)(T - 1) * TILE + ft * 4) = a;
                }
            }
        }
        __syncthreads();
    }

    // ---- epilogue: flush v_pre/v/s + logits of tile 127 (buffer 1) ----
    if (tid >= 192) {
        const int ft = tid - 192;
        const int r0 = ft >> 4, tq = ft & 15;
        const float* vpb = tvp + ((NTILES - 1) & 1) * TSZ;
        const size_t pcol = (size_t)(NTILES - 1) * TILE + tq * 4;
        float4 mx = make_float4(-1e30f, -1e30f, -1e30f, -1e30f);
#pragma unroll
        for (int i = 0; i < 16; ++i) {
            const int r = r0 + 4 * i;
            const size_t grow = (size_t)(frow0 + r) * LL;
            float4 vq = *(const float4*)(vpb + r * RS + tq * 4);
            float4 sq, vn;
            sq.x = (vq.x >= 1.0f) ? 1.0f : 0.0f;
            sq.y = (vq.y >= 1.0f) ? 1.0f : 0.0f;
            sq.z = (vq.z >= 1.0f) ? 1.0f : 0.0f;
            sq.w = (vq.w >= 1.0f) ? 1.0f : 0.0f;
            vn.x = (vq.x >= 1.0f) ? 0.0f : vq.x;
            vn.y = (vq.y >= 1.0f) ? 0.0f : vq.y;
            vn.z = (vq.z >= 1.0f) ? 0.0f : vq.z;
            vn.w = (vq.w >= 1.0f) ? 0.0f : vq.w;
            stcs4(vpre_out + grow + pcol, vq);
            stcs4(v_out    + grow + pcol, vn);
            stcs4(s_out    + grow + pcol, sq);
            mx = max4(mx, vq);
        }
        *(float4*)(red + ft * 4) = mx;
        asm volatile("bar.sync 3, 64;" ::: "memory");
        if (ft < 16) {
            float4 a  = *(float4*)(red + ft * 4);
            float4 b4 = *(float4*)(red + (16 + ft) * 4);
            float4 c4 = *(float4*)(red + (32 + ft) * 4);
            float4 d4 = *(float4*)(red + (48 + ft) * 4);
            a = max4(max4(a, b4), max4(c4, d4));
            *(float4*)(prow + (size_t)(NTILES - 1) * TILE + ft * 4) = a;
        }
    }
}

// ---------------------------------------------------------------------------
// Combine the two filter-half partial maxes into logits (vectorized float4).
// ---------------------------------------------------------------------------
__global__ __launch_bounds__(256) void logits_kernel(float* __restrict__ logits)
{
    int i = blockIdx.x * blockDim.x + threadIdx.x;   // 0 .. BB*LL/4-1
    int b = i >> 11;                                 // 2048 float4 per batch
    int l4 = i & 2047;
    const float4* p0 = (const float4*)(g_partial + (size_t)(2 * b) * LL) + l4;
    const float4* p1 = (const float4*)(g_partial + (size_t)(2 * b + 1) * LL) + l4;
    float4 a = *p0, c = *p1;
    float4 m = max4(a, c);
    m.x -= 1.0f; m.y -= 1.0f; m.z -= 1.0f; m.w -= 1.0f;
    stcs4(logits + (size_t)b * LL + l4 * 4, m);
}

extern "C" void kernel_launch(void* const* d_in, const int* in_sizes, int n_in,
                              void* d_out, int out_size)
{
    const float* x    = (const float*)d_in[0];
    const float* W    = (const float*)d_in[1];
    const float* bias = (const float*)d_in[2];
    float* out = (float*)d_out;

    const size_t N = (size_t)BB * FF * LL;   // 67,108,864
    float* I    = out;
    float* vpre = out + N;
    float* vv   = out + 2 * N;
    float* ss   = out + 3 * N;
    float* lg   = out + 4 * N;

    const int smem_bytes = (4 * TSZ + 84 + 84 + 256) * sizeof(float); // ~71.3KB
    cudaFuncSetAttribute(snn_fused,
                         cudaFuncAttributeMaxDynamicSharedMemorySize, smem_bytes);

    snn_fused<<<128, 256, smem_bytes>>>(x, W, bias, I, vpre, vv, ss);
    logits_kernel<<<(BB * LL / 4) / 256, 256>>>(lg);
}

// round 6
// speedup vs baseline: 2.7242x; 1.0221x over previous
#include <cuda_runtime.h>

#define BB 64
#define FF 128
#define LL 8192
#define KK 16
#define TILE 128
#define NTILES (LL / TILE)      // 64
#define RS 132                  // padded SMEM row stride (floats)
#define TSZ (64 * RS)           // 8448 floats per tile buffer

typedef unsigned long long u64;

__device__ float g_partial[128 * LL];   // per-(batch,half) partial logits max

__device__ __forceinline__ u64 fma2(u64 a, u64 b, u64 c) {
    u64 d;
    asm("fma.rn.f32x2 %0, %1, %2, %3;" : "=l"(d) : "l"(a), "l"(b), "l"(c));
    return d;
}
__device__ __forceinline__ u64 pack2(float lo, float hi) {
    u64 d; asm("mov.b64 %0, {%1, %2};" : "=l"(d) : "f"(lo), "f"(hi)); return d;
}
__device__ __forceinline__ void unpack2(u64 v, float& lo, float& hi) {
    asm("mov.b64 {%0, %1}, %2;" : "=f"(lo), "=f"(hi) : "l"(v));
}
__device__ __forceinline__ void stcs4(float* p, float4 v) {
    asm volatile("st.global.cs.v4.f32 [%0], {%1,%2,%3,%4};"
                 :: "l"(p), "f"(v.x), "f"(v.y), "f"(v.z), "f"(v.w) : "memory");
}
__device__ __forceinline__ float4 max4(float4 a, float4 b) {
    return make_float4(fmaxf(a.x, b.x), fmaxf(a.y, b.y),
                       fmaxf(a.z, b.z), fmaxf(a.w, b.w));
}

// ---------------------------------------------------------------------------
// conv: one column half (16 quads, 64 cols) for fixed filter f. f32x2 FMAs.
// xs[p] = x[tile*128 - 15 + p]; xsh[q] = xs[q+1] (odd-parity pairs).
// ---------------------------------------------------------------------------
__device__ __forceinline__ void conv_do(
    int qh, const float* __restrict__ xs, const float* __restrict__ xsh,
    const u64* __restrict__ w2, u64 bias2, float* __restrict__ irow)
{
#pragma unroll
    for (int j = 0; j < 16; ++j) {
        const int lt4 = qh * 64 + 4 * j;     // even
        u64 P[18];
#pragma unroll
        for (int m = 0; m < 18; ++m) {
            int base = lt4 + m;              // parity == m parity
            P[m] = (m & 1) ? *(const u64*)(xsh + (base - 1))
                           : *(const u64*)(xs + base);
        }
        u64 a01 = bias2, a23 = bias2;
#pragma unroll
        for (int k = 0; k < KK; ++k) {
            a01 = fma2(w2[k], P[k],     a01);
            a23 = fma2(w2[k], P[k + 2], a23);
        }
        float o0, o1, o2, o3;
        unpack2(a01, o0, o1);
        unpack2(a23, o2, o3);
        *(float4*)(irow + lt4) = make_float4(o0, o1, o2, o3);
    }
}

// ---------------------------------------------------------------------------
// Fused conv + LIF + coalesced streaming stores + fused logits partial max.
// Grid 128 = (batch, filter-half), 256 threads:
//   tid   0- 63 : chain warps  — LIF recurrence, write v_pre tiles to SMEM
//   tid  64-191 : conv warps   — f32x2 conv of tile T+1 into SMEM (dbl-buf)
//   tid 192-255 : flush warps  — STG I(T); STG v_pre/v/s(T-1) with derive;
//                                running column-max -> g_partial
// ---------------------------------------------------------------------------
__global__ __launch_bounds__(256, 1) void snn_fused(
    const float* __restrict__ x, const float* __restrict__ W,
    const float* __restrict__ bias,
    float* __restrict__ I_out, float* __restrict__ vpre_out,
    float* __restrict__ v_out, float* __restrict__ s_out)
{
    extern __shared__ float sm[];
    float* Ibuf = sm;                 // 2*TSZ
    float* tvp  = sm + 2 * TSZ;       // 2*TSZ
    float* xs   = sm + 4 * TSZ;       // 144 (143 used)
    float* xsh  = xs + 144;           // 144
    float* red  = xsh + 144;          // 256

    const int tid   = threadIdx.x;
    const int b     = blockIdx.x >> 1;
    const int h     = blockIdx.x & 1;
    const int frow0 = b * FF + h * 64;          // OUTPUT row base (batch-dep)
    const float* __restrict__ xb = x + (size_t)b * LL;
    float* __restrict__ prow = g_partial + (size_t)blockIdx.x * LL;

    // conv-thread persistent state (filter index is batch-INDEPENDENT)
    u64 w2[KK];
    u64 bias2 = 0;
    int f_loc = 0, qh = 0;
    if (tid >= 64 && tid < 192) {
        const int p = tid - 64;
        f_loc = p >> 1; qh = p & 1;
        const int fflt = h * 64 + f_loc;        // filter index 0..127
#pragma unroll
        for (int k = 0; k < KK; ++k) {
            const float w = W[fflt * KK + k];
            w2[k] = pack2(w, w);
        }
        const float bv = bias[fflt];
        bias2 = pack2(bv, bv);
    }

    // ---- prologue: stage xs(tile0), conv tile0 -> Ibuf[0] ----
    if (tid >= 64 && tid < 192) {
        const int p = tid - 64;
        {
            int g = p - 15;
            float val = (g >= 0) ? xb[g] : 0.0f;
            xs[p] = val;
            if (p >= 1) xsh[p - 1] = val;
        }
        if (p < 15) {
            int idx = 128 + p;
            float val = xb[idx - 15];
            xs[idx] = val;
            xsh[idx - 1] = val;
        }
        asm volatile("bar.sync 1, 128;" ::: "memory");
        conv_do(qh, xs, xsh, w2, bias2, Ibuf + f_loc * RS);
    }
    __syncthreads();

    float vchain = 0.0f;

    for (int T = 0; T < NTILES; ++T) {
        const int buf = T & 1;
        if (tid < 64) {
            // ---------------- chain ----------------
            const float* ir = Ibuf + buf * TSZ + tid * RS;
            float* vr = tvp + buf * TSZ + tid * RS;
            float4 cur = *(const float4*)ir;
#pragma unroll
            for (int q = 0; q < 32; ++q) {
                float4 nxt = (q < 31) ? *(const float4*)(ir + 4 * (q + 1)) : cur;
                const float c0 = 0.2f * cur.x, c1 = 0.2f * cur.y;
                const float c2 = 0.2f * cur.z, c3 = 0.2f * cur.w;
                float vp0 = fmaf(vchain, 0.8f, c0);
                vchain = (vp0 >= 1.0f) ? 0.0f : vp0;
                float vp1 = fmaf(vchain, 0.8f, c1);
                vchain = (vp1 >= 1.0f) ? 0.0f : vp1;
                float vp2 = fmaf(vchain, 0.8f, c2);
                vchain = (vp2 >= 1.0f) ? 0.0f : vp2;
                float vp3 = fmaf(vchain, 0.8f, c3);
                vchain = (vp3 >= 1.0f) ? 0.0f : vp3;
                *(float4*)(vr + 4 * q) = make_float4(vp0, vp1, vp2, vp3);
                cur = nxt;
            }
        } else if (tid < 192) {
            // ---------------- conv ----------------
            const int p = tid - 64;
            if (T + 1 < NTILES) {
                {
                    int g = (T + 1) * TILE - 15 + p;   // always >= 113, valid
                    float val = xb[g];
                    xs[p] = val;
                    if (p >= 1) xsh[p - 1] = val;
                }
                if (p < 15) {
                    int idx = 128 + p;
                    float val = xb[(T + 1) * TILE - 15 + idx];
                    xs[idx] = val;
                    xsh[idx - 1] = val;
                }
                asm volatile("bar.sync 1, 128;" ::: "memory");
                conv_do(qh, xs, xsh, w2, bias2,
                        Ibuf + ((T + 1) & 1) * TSZ + f_loc * RS);
            }
        } else {
            // ---------------- flush ----------------
            const int ft = tid - 192;
            const int r0 = ft >> 5, tq = ft & 31;    // warp covers full rows
            const float* ib  = Ibuf + buf * TSZ;
            const float* vpb = tvp + (buf ^ 1) * TSZ;
            const size_t tcol = (size_t)T * TILE + tq * 4;
            const size_t pcol = (size_t)(T - 1) * TILE + tq * 4;
            float4 mx = make_float4(-1e30f, -1e30f, -1e30f, -1e30f);
#pragma unroll
            for (int i = 0; i < 32; ++i) {
                const int r = r0 + 2 * i;
                const size_t grow = (size_t)(frow0 + r) * LL;
                float4 iq = *(const float4*)(ib + r * RS + tq * 4);
                stcs4(I_out + grow + tcol, iq);
                if (T >= 1) {
                    float4 vq = *(const float4*)(vpb + r * RS + tq * 4);
                    float4 sq, vn;
                    sq.x = (vq.x >= 1.0f) ? 1.0f : 0.0f;
                    sq.y = (vq.y >= 1.0f) ? 1.0f : 0.0f;
                    sq.z = (vq.z >= 1.0f) ? 1.0f : 0.0f;
                    sq.w = (vq.w >= 1.0f) ? 1.0f : 0.0f;
                    vn.x = (vq.x >= 1.0f) ? 0.0f : vq.x;
                    vn.y = (vq.y >= 1.0f) ? 0.0f : vq.y;
                    vn.z = (vq.z >= 1.0f) ? 0.0f : vq.z;
                    vn.w = (vq.w >= 1.0f) ? 0.0f : vq.w;
                    stcs4(vpre_out + grow + pcol, vq);
                    stcs4(v_out    + grow + pcol, vn);
                    stcs4(s_out    + grow + pcol, sq);
                    mx = max4(mx, vq);
                }
            }
            if (T >= 1) {
                *(float4*)(red + ft * 4) = mx;
                asm volatile("bar.sync 3, 64;" ::: "memory");
                if (ft < 32) {
                    float4 a  = *(float4*)(red + ft * 4);
                    float4 b4 = *(float4*)(red + (32 + ft) * 4);
                    a = max4(a, b4);
                    *(float4*)(prow + (size_t)(T - 1) * TILE + ft * 4) = a;
                }
            }
        }
        __syncthreads();
    }

    // ---- epilogue: flush v_pre/v/s + logits of tile 63 (buffer 1) ----
    if (tid >= 192) {
        const int ft = tid - 192;
        const int r0 = ft >> 5, tq = ft & 31;
        const float* vpb = tvp + ((NTILES - 1) & 1) * TSZ;
        const size_t pcol = (size_t)(NTILES - 1) * TILE + tq * 4;
        float4 mx = make_float4(-1e30f, -1e30f, -1e30f, -1e30f);
#pragma unroll
        for (int i = 0; i < 32; ++i) {
            const int r = r0 + 2 * i;
            const size_t grow = (size_t)(frow0 + r) * LL;
            float4 vq = *(const float4*)(vpb + r * RS + tq * 4);
            float4 sq, vn;
            sq.x = (vq.x >= 1.0f) ? 1.0f : 0.0f;
            sq.y = (vq.y >= 1.0f) ? 1.0f : 0.0f;
            sq.z = (vq.z >= 1.0f) ? 1.0f : 0.0f;
            sq.w = (vq.w >= 1.0f) ? 1.0f : 0.0f;
            vn.x = (vq.x >= 1.0f) ? 0.0f : vq.x;
            vn.y = (vq.y >= 1.0f) ? 0.0f : vq.y;
            vn.z = (vq.z >= 1.0f) ? 0.0f : vq.z;
            vn.w = (vq.w >= 1.0f) ? 0.0f : vq.w;
            stcs4(vpre_out + grow + pcol, vq);
            stcs4(v_out    + grow + pcol, vn);
            stcs4(s_out    + grow + pcol, sq);
            mx = max4(mx, vq);
        }
        *(float4*)(red + ft * 4) = mx;
        asm volatile("bar.sync 3, 64;" ::: "memory");
        if (ft < 32) {
            float4 a  = *(float4*)(red + ft * 4);
            float4 b4 = *(float4*)(red + (32 + ft) * 4);
            a = max4(a, b4);
            *(float4*)(prow + (size_t)(NTILES - 1) * TILE + ft * 4) = a;
        }
    }
}

// ---------------------------------------------------------------------------
// Combine the two filter-half partial maxes into logits (vectorized float4).
// ---------------------------------------------------------------------------
__global__ __launch_bounds__(256) void logits_kernel(float* __restrict__ logits)
{
    int i = blockIdx.x * blockDim.x + threadIdx.x;   // 0 .. BB*LL/4-1
    int b = i >> 11;                                 // 2048 float4 per batch
    int l4 = i & 2047;
    const float4* p0 = (const float4*)(g_partial + (size_t)(2 * b) * LL) + l4;
    const float4* p1 = (const float4*)(g_partial + (size_t)(2 * b + 1) * LL) + l4;
    float4 a = *p0, c = *p1;
    float4 m = max4(a, c);
    m.x -= 1.0f; m.y -= 1.0f; m.z -= 1.0f; m.w -= 1.0f;
    stcs4(logits + (size_t)b * LL + l4 * 4, m);
}

extern "C" void kernel_launch(void* const* d_in, const int* in_sizes, int n_in,
                              void* d_out, int out_size)
{
    const float* x    = (const float*)d_in[0];
    const float* W    = (const float*)d_in[1];
    const float* bias = (const float*)d_in[2];
    float* out = (float*)d_out;

    const size_t N = (size_t)BB * FF * LL;   // 67,108,864
    float* I    = out;
    float* vpre = out + N;
    float* vv   = out + 2 * N;
    float* ss   = out + 3 * N;
    float* lg   = out + 4 * N;

    const int smem_bytes = (4 * TSZ + 144 + 144 + 256) * sizeof(float); // ~137.4KB
    cudaFuncSetAttribute(snn_fused,
                         cudaFuncAttributeMaxDynamicSharedMemorySize, smem_bytes);

    snn_fused<<<128, 256, smem_bytes>>>(x, W, bias, I, vpre, vv, ss);
    logits_kernel<<<(BB * LL / 4) / 256, 256>>>(lg);
}